// round 6
// baseline (speedup 1.0000x reference)
#include <cuda_runtime.h>
#include <math.h>

#define Bsz 256
#define Tt  128
#define Nn  512
#define Hh  128
#define G4  512   // 4*H
#define KC  96    // w_hhT rows cached in recurrence smem (96*512*4 = 192 KB)

// Scratch: 64 MB gate preactivations + transposed w_hh (device globals — no runtime alloc)
__device__ float g_Gpre[(size_t)Bsz * Tt * G4];
__device__ float g_whhT[Hh * G4];

// ---------------------------------------------------------------------------
// w_hh (4H, H) -> w_hhT (H, 4H) so the recurrence matvec loads are coalesced
// ---------------------------------------------------------------------------
__global__ void k_transpose_whh(const float* __restrict__ whh) {
    int idx = blockIdx.x * blockDim.x + threadIdx.x;
    if (idx < Hh * G4) {
        int k = idx >> 9;     // 0..127
        int j = idx & 511;    // 0..511
        g_whhT[idx] = whh[j * Hh + k];
    }
}

// ---------------------------------------------------------------------------
// Per-batch: x_score = sum_t X[b,t,n]*w_x[t]; alpha = softmax_n(x_score);
// Xt[b,t,n] = alpha[b,n] * X[b,t,n]   (alpha is time-invariant)
// One block per batch, 512 threads (n index).
// ---------------------------------------------------------------------------
__global__ __launch_bounds__(512) void k_alpha(const float* __restrict__ X,
                                               const float* __restrict__ attn_w,
                                               float* __restrict__ Xt) {
    int b = blockIdx.x;
    int n = threadIdx.x;
    __shared__ float wx[Tt];
    __shared__ float redm[17];
    __shared__ float reds[17];
    if (n < Tt) wx[n] = attn_w[2 * Hh + n];
    __syncthreads();

    const float* Xb = X + (size_t)b * Tt * Nn;
    float acc = 0.f;
#pragma unroll 8
    for (int t = 0; t < Tt; t++)
        acc = fmaf(Xb[t * Nn + n], wx[t], acc);

    // block max over 512 values
    float v = acc;
#pragma unroll
    for (int o = 16; o > 0; o >>= 1)
        v = fmaxf(v, __shfl_xor_sync(0xffffffffu, v, o));
    if ((n & 31) == 0) redm[n >> 5] = v;
    __syncthreads();
    if (n < 32) {
        float m = (n < 16) ? redm[n] : -3.402823466e38f;
#pragma unroll
        for (int o = 16; o > 0; o >>= 1)
            m = fmaxf(m, __shfl_xor_sync(0xffffffffu, m, o));
        if (n == 0) redm[16] = m;
    }
    __syncthreads();
    float mx = redm[16];

    float e = __expf(acc - mx);
    // block sum
    v = e;
#pragma unroll
    for (int o = 16; o > 0; o >>= 1)
        v += __shfl_xor_sync(0xffffffffu, v, o);
    if ((n & 31) == 0) reds[n >> 5] = v;
    __syncthreads();
    if (n < 32) {
        float s = (n < 16) ? reds[n] : 0.f;
#pragma unroll
        for (int o = 16; o > 0; o >>= 1)
            s += __shfl_xor_sync(0xffffffffu, s, o);
        if (n == 0) reds[16] = s;
    }
    __syncthreads();
    float alpha = e / reds[16];

    float* Ot = Xt + (size_t)b * Tt * Nn;
#pragma unroll 4
    for (int t = 0; t < Tt; t++)
        Ot[t * Nn + n] = alpha * Xb[t * Nn + n];
}

// ---------------------------------------------------------------------------
// Gpre(32768,512) = Xt(32768,512) @ w_ih^T(512,512) + (b_ih + b_hh)
// Classic 128x128x8 SGEMM-NT (both operands K-contiguous), 256 threads,
// 8x8 microtile, register prefetch of next K-slab.
// grid = (4, 256): bn inner so the 4 column-blocks sharing an A-tile run
// co-resident -> A read once from HBM, reused in L2.
// ---------------------------------------------------------------------------
__global__ __launch_bounds__(256) void k_gemm(const float* __restrict__ A,
                                              const float* __restrict__ Bw,
                                              const float* __restrict__ bih,
                                              const float* __restrict__ bhh) {
    __shared__ float As[8][128];
    __shared__ float Bs[8][128];
    int tid = threadIdx.x;
    int bn = blockIdx.x;   // 0..3
    int bm = blockIdx.y;   // 0..255
    const float* Ab = A  + (size_t)bm * 128 * 512;
    const float* Bb = Bw + (size_t)bn * 128 * 512;
    int lr = tid >> 1;          // row within tile (0..127)
    int lc = (tid & 1) * 4;     // k offset (0 or 4)
    int tm = (tid >> 4) * 8;    // 0..120
    int tn = (tid & 15) * 8;    // 0..120

    float acc[8][8];
#pragma unroll
    for (int i = 0; i < 8; i++)
#pragma unroll
        for (int j = 0; j < 8; j++) acc[i][j] = 0.f;

    float4 pa = *(const float4*)(Ab + lr * 512 + lc);
    float4 pb = *(const float4*)(Bb + lr * 512 + lc);

    for (int k0 = 0; k0 < 512; k0 += 8) {
        As[lc + 0][lr] = pa.x; As[lc + 1][lr] = pa.y;
        As[lc + 2][lr] = pa.z; As[lc + 3][lr] = pa.w;
        Bs[lc + 0][lr] = pb.x; Bs[lc + 1][lr] = pb.y;
        Bs[lc + 2][lr] = pb.z; Bs[lc + 3][lr] = pb.w;
        __syncthreads();
        if (k0 + 8 < 512) {
            pa = *(const float4*)(Ab + lr * 512 + k0 + 8 + lc);
            pb = *(const float4*)(Bb + lr * 512 + k0 + 8 + lc);
        }
#pragma unroll
        for (int k = 0; k < 8; k++) {
            float ra[8], rb[8];
            *(float4*)(ra)     = *(const float4*)(&As[k][tm]);
            *(float4*)(ra + 4) = *(const float4*)(&As[k][tm + 4]);
            *(float4*)(rb)     = *(const float4*)(&Bs[k][tn]);
            *(float4*)(rb + 4) = *(const float4*)(&Bs[k][tn + 4]);
#pragma unroll
            for (int i = 0; i < 8; i++)
#pragma unroll
                for (int j = 0; j < 8; j++)
                    acc[i][j] = fmaf(ra[i], rb[j], acc[i][j]);
        }
        __syncthreads();
    }

    float bias[8];
#pragma unroll
    for (int j = 0; j < 8; j++)
        bias[j] = bih[bn * 128 + tn + j] + bhh[bn * 128 + tn + j];

#pragma unroll
    for (int i = 0; i < 8; i++) {
        float* Crow = g_Gpre + ((size_t)(bm * 128 + tm + i)) * 512 + bn * 128 + tn;
        float4 o0 = make_float4(acc[i][0] + bias[0], acc[i][1] + bias[1],
                                acc[i][2] + bias[2], acc[i][3] + bias[3]);
        float4 o1 = make_float4(acc[i][4] + bias[4], acc[i][5] + bias[5],
                                acc[i][6] + bias[6], acc[i][7] + bias[7]);
        *(float4*)(Crow)     = o0;
        *(float4*)(Crow + 4) = o1;
    }
}

// ---------------------------------------------------------------------------
// LSTM recurrence. Batches independent: 128 blocks x 2 batches, 512 threads.
// w_hhT rows [0,KC) cached in dynamic smem (192 KB); rows [KC,128) stream
// from L2. Matvec phase: thread -> (bi = tid>>8, gate pair jj = (tid&255)*2).
// Update phase: threads 0..255 -> (bi = tid>>7, hid = tid&127).
// ---------------------------------------------------------------------------
__device__ __forceinline__ float sigm(float x) { return 1.f / (1.f + __expf(-x)); }

__global__ __launch_bounds__(512) void k_recur(float* __restrict__ Xe) {
    extern __shared__ float sm[];
    float* ws = sm;                 // [KC][512]
    float* hs = ws + KC * G4;       // [2][128]
    float* cs = hs + 2 * Hh;        // [2][128]
    float* gs = cs + 2 * Hh;        // [2][512]

    int tid = threadIdx.x;
    int b0  = blockIdx.x * 2;

    // stage weight rows [0,KC) into smem
    for (int i = tid; i < KC * G4 / 4; i += 512)
        ((float4*)ws)[i] = ((const float4*)g_whhT)[i];
    if (tid < 2 * Hh) { hs[tid] = 0.f; cs[tid] = 0.f; }
    __syncthreads();

    int bi = tid >> 8;            // 0..1
    int jj = (tid & 255) * 2;     // 0..510

    const float* Gb  = g_Gpre + (size_t)(b0 + bi) * Tt * G4 + jj;
    const float* wgl = g_whhT + KC * G4 + jj;
    const float* hb  = hs + bi * Hh;

    for (int t = 0; t < Tt; t++) {
        float2 acc = *(const float2*)(Gb + (size_t)t * G4);
#pragma unroll 8
        for (int k = 0; k < KC; k++) {
            float2 w = *(const float2*)(ws + k * G4 + jj);
            float h = hb[k];
            acc.x = fmaf(w.x, h, acc.x);
            acc.y = fmaf(w.y, h, acc.y);
        }
#pragma unroll 8
        for (int k = 0; k < Hh - KC; k++) {
            float2 w = *(const float2*)(wgl + k * G4);
            float h = hb[KC + k];
            acc.x = fmaf(w.x, h, acc.x);
            acc.y = fmaf(w.y, h, acc.y);
        }
        *(float2*)(gs + bi * G4 + jj) = acc;
        __syncthreads();

        if (tid < 256) {
            int b2  = tid >> 7;       // 0..1
            int hid = tid & 127;
            const float* gb = gs + b2 * G4;
            float gi = gb[hid];
            float gf = gb[Hh + hid];
            float gg = gb[2 * Hh + hid];
            float go = gb[3 * Hh + hid];
            float cn = sigm(gf) * cs[b2 * Hh + hid] + sigm(gi) * tanhf(gg);
            float hn = sigm(go) * tanhf(cn);
            cs[b2 * Hh + hid] = cn;
            hs[b2 * Hh + hid] = hn;
            Xe[((size_t)(b0 + b2) * Tt + t) * Hh + hid] = hn;
        }
        __syncthreads();
    }
}

// ---------------------------------------------------------------------------
extern "C" void kernel_launch(void* const* d_in, const int* in_sizes, int n_in,
                              void* d_out, int out_size) {
    const float* X      = (const float*)d_in[0];
    const float* attn_w = (const float*)d_in[1];
    // d_in[2] = attn_b: dead (softmax shift-invariance), as are attn_w[0:2H]
    const float* w_ih   = (const float*)d_in[3];
    const float* w_hh   = (const float*)d_in[4];
    const float* b_ih   = (const float*)d_in[5];
    const float* b_hh   = (const float*)d_in[6];

    float* out = (float*)d_out;
    float* Xt  = out;                                  // (B,T,N)
    float* Xe  = out + (size_t)Bsz * Tt * Nn;          // (B,T,H)

    const int recur_smem = (KC * G4 + 2 * Hh + 2 * Hh + 2 * G4) * (int)sizeof(float);
    static int attr_done = 0;
    (void)attr_done;
    cudaFuncSetAttribute(k_recur, cudaFuncAttributeMaxDynamicSharedMemorySize,
                         recur_smem);

    k_transpose_whh<<<(Hh * G4 + 255) / 256, 256>>>(w_hh);
    k_alpha<<<Bsz, 512>>>(X, attn_w, Xt);
    k_gemm<<<dim3(4, Bsz * Tt / 128), 256>>>(Xt, w_ih, b_ih, b_hh);
    k_recur<<<Bsz / 2, 512, recur_smem>>>(Xe);
}

// round 10
// speedup vs baseline: 1.4588x; 1.4588x over previous
#include <cuda_runtime.h>
#include <math.h>

#define Bsz 256
#define Tt  128
#define Nn  512
#define Hh  128
#define G4  512   // 4*H
#define KC  96    // w_hhT rows resident in recurrence smem (96*512*4 = 192 KB)

// Scratch: 64 MB gate preactivations + transposed w_hh (device globals — no runtime alloc)
__device__ float g_Gpre[(size_t)Bsz * Tt * G4];
__device__ float g_whhT[Hh * G4];

// ---------------------------------------------------------------------------
// w_hh (4H, H) -> w_hhT (H, 4H) so the recurrence matvec loads are coalesced
// ---------------------------------------------------------------------------
__global__ void k_transpose_whh(const float* __restrict__ whh) {
    int idx = blockIdx.x * blockDim.x + threadIdx.x;
    if (idx < Hh * G4) {
        int k = idx >> 9;     // 0..127
        int j = idx & 511;    // 0..511
        g_whhT[idx] = whh[j * Hh + k];
    }
}

// ---------------------------------------------------------------------------
// Per-batch: x_score = sum_t X[b,t,n]*w_x[t]; alpha = softmax_n(x_score);
// Xt[b,t,n] = alpha[b,n] * X[b,t,n]   (alpha is time-invariant)
// ---------------------------------------------------------------------------
__global__ __launch_bounds__(512) void k_alpha(const float* __restrict__ X,
                                               const float* __restrict__ attn_w,
                                               float* __restrict__ Xt) {
    int b = blockIdx.x;
    int n = threadIdx.x;
    __shared__ float wx[Tt];
    __shared__ float redm[17];
    __shared__ float reds[17];
    if (n < Tt) wx[n] = attn_w[2 * Hh + n];
    __syncthreads();

    const float* Xb = X + (size_t)b * Tt * Nn;
    float acc = 0.f;
#pragma unroll 8
    for (int t = 0; t < Tt; t++)
        acc = fmaf(Xb[t * Nn + n], wx[t], acc);

    float v = acc;
#pragma unroll
    for (int o = 16; o > 0; o >>= 1)
        v = fmaxf(v, __shfl_xor_sync(0xffffffffu, v, o));
    if ((n & 31) == 0) redm[n >> 5] = v;
    __syncthreads();
    if (n < 32) {
        float m = (n < 16) ? redm[n] : -3.402823466e38f;
#pragma unroll
        for (int o = 16; o > 0; o >>= 1)
            m = fmaxf(m, __shfl_xor_sync(0xffffffffu, m, o));
        if (n == 0) redm[16] = m;
    }
    __syncthreads();
    float mx = redm[16];

    float e = __expf(acc - mx);
    v = e;
#pragma unroll
    for (int o = 16; o > 0; o >>= 1)
        v += __shfl_xor_sync(0xffffffffu, v, o);
    if ((n & 31) == 0) reds[n >> 5] = v;
    __syncthreads();
    if (n < 32) {
        float s = (n < 16) ? reds[n] : 0.f;
#pragma unroll
        for (int o = 16; o > 0; o >>= 1)
            s += __shfl_xor_sync(0xffffffffu, s, o);
        if (n == 0) reds[16] = s;
    }
    __syncthreads();
    float alpha = e / reds[16];

    float* Ot = Xt + (size_t)b * Tt * Nn;
#pragma unroll 4
    for (int t = 0; t < Tt; t++)
        Ot[t * Nn + n] = alpha * Xb[t * Nn + n];
}

// ---------------------------------------------------------------------------
// Gpre(32768,512) = Xt(32768,512) @ w_ih^T(512,512) + (b_ih + b_hh)
// 128x128x8 SGEMM-NT, 256 threads, 8x8 microtile, register prefetch,
// DOUBLE-BUFFERED smem tiles (one __syncthreads per K-slab instead of two).
// ---------------------------------------------------------------------------
__global__ __launch_bounds__(256) void k_gemm(const float* __restrict__ A,
                                              const float* __restrict__ Bw,
                                              const float* __restrict__ bih,
                                              const float* __restrict__ bhh) {
    __shared__ float As[2][8][128];
    __shared__ float Bs[2][8][128];
    int tid = threadIdx.x;
    int bn = blockIdx.x;   // 0..3
    int bm = blockIdx.y;   // 0..255
    const float* Ab = A  + (size_t)bm * 128 * 512;
    const float* Bb = Bw + (size_t)bn * 128 * 512;
    int lr = tid >> 1;          // row within tile (0..127)
    int lc = (tid & 1) * 4;     // k offset (0 or 4)
    int tm = (tid >> 4) * 8;    // 0..120
    int tn = (tid & 15) * 8;    // 0..120

    float acc[8][8];
#pragma unroll
    for (int i = 0; i < 8; i++)
#pragma unroll
        for (int j = 0; j < 8; j++) acc[i][j] = 0.f;

    // prologue: load slab 0 into buffer 0
    {
        float4 pa = *(const float4*)(Ab + lr * 512 + lc);
        float4 pb = *(const float4*)(Bb + lr * 512 + lc);
        As[0][lc + 0][lr] = pa.x; As[0][lc + 1][lr] = pa.y;
        As[0][lc + 2][lr] = pa.z; As[0][lc + 3][lr] = pa.w;
        Bs[0][lc + 0][lr] = pb.x; Bs[0][lc + 1][lr] = pb.y;
        Bs[0][lc + 2][lr] = pb.z; Bs[0][lc + 3][lr] = pb.w;
    }
    __syncthreads();

    int buf = 0;
    for (int k0 = 0; k0 < 512; k0 += 8) {
        float4 pa, pb;
        bool more = (k0 + 8 < 512);
        if (more) {
            pa = *(const float4*)(Ab + lr * 512 + k0 + 8 + lc);
            pb = *(const float4*)(Bb + lr * 512 + k0 + 8 + lc);
        }
#pragma unroll
        for (int k = 0; k < 8; k++) {
            float ra[8], rb[8];
            *(float4*)(ra)     = *(const float4*)(&As[buf][k][tm]);
            *(float4*)(ra + 4) = *(const float4*)(&As[buf][k][tm + 4]);
            *(float4*)(rb)     = *(const float4*)(&Bs[buf][k][tn]);
            *(float4*)(rb + 4) = *(const float4*)(&Bs[buf][k][tn + 4]);
#pragma unroll
            for (int i = 0; i < 8; i++)
#pragma unroll
                for (int j = 0; j < 8; j++)
                    acc[i][j] = fmaf(ra[i], rb[j], acc[i][j]);
        }
        if (more) {
            int nb = buf ^ 1;
            As[nb][lc + 0][lr] = pa.x; As[nb][lc + 1][lr] = pa.y;
            As[nb][lc + 2][lr] = pa.z; As[nb][lc + 3][lr] = pa.w;
            Bs[nb][lc + 0][lr] = pb.x; Bs[nb][lc + 1][lr] = pb.y;
            Bs[nb][lc + 2][lr] = pb.z; Bs[nb][lc + 3][lr] = pb.w;
            __syncthreads();
            buf = nb;
        }
    }

    float bias[8];
#pragma unroll
    for (int j = 0; j < 8; j++)
        bias[j] = bih[bn * 128 + tn + j] + bhh[bn * 128 + tn + j];

#pragma unroll
    for (int i = 0; i < 8; i++) {
        float* Crow = g_Gpre + ((size_t)(bm * 128 + tm + i)) * 512 + bn * 128 + tn;
        float4 o0 = make_float4(acc[i][0] + bias[0], acc[i][1] + bias[1],
                                acc[i][2] + bias[2], acc[i][3] + bias[3]);
        float4 o1 = make_float4(acc[i][4] + bias[4], acc[i][5] + bias[5],
                                acc[i][6] + bias[6], acc[i][7] + bias[7]);
        *(float4*)(Crow)     = o0;
        *(float4*)(Crow + 4) = o1;
    }
}

// ---------------------------------------------------------------------------
// LSTM recurrence, crossbar-minimized split-K formulation.
// 128 blocks x 2 batches, 512 threads.
//   thread (kk = tid>>7, jg = tid&127): gates j4 = jg*4, BOTH batches,
//   k-slice [kk*32, kk*32+32). One LDS.128 weight load feeds 8 FMAs.
//   kgroups 0..2 read weights from smem (192 KB); kgroup 3 streams its
//   64 KB from L2 (stays hot across all 128 steps).
//   Partials reduced in smem; Gpre prefetched via LDG at step top so DRAM
//   latency hides under the matvec.
// ---------------------------------------------------------------------------
__device__ __forceinline__ float sigm(float x) { return 1.f / (1.f + __expf(-x)); }

__device__ __forceinline__ void fma4(float4& acc, const float4& wv, float hv) {
    acc.x = fmaf(wv.x, hv, acc.x);
    acc.y = fmaf(wv.y, hv, acc.y);
    acc.z = fmaf(wv.z, hv, acc.z);
    acc.w = fmaf(wv.w, hv, acc.w);
}

__global__ __launch_bounds__(512) void k_recur(float* __restrict__ Xe) {
    extern __shared__ float sm[];
    float* ws = sm;                     // [KC][512]
    float* pg = ws + KC * G4;           // [4][2][512] partials
    float* hs = pg + 4 * 2 * G4;        // [2][128]
    float* cs = hs + 2 * Hh;            // [2][128]

    int tid = threadIdx.x;
    int b0  = blockIdx.x * 2;

    // stage weight rows [0,KC) into smem
    for (int i = tid; i < KC * G4 / 4; i += 512)
        ((float4*)ws)[i] = ((const float4*)g_whhT)[i];
    if (tid < 2 * Hh) { hs[tid] = 0.f; cs[tid] = 0.f; }
    __syncthreads();

    int kk    = tid >> 7;        // 0..3 k-group
    int jg    = tid & 127;       // 0..127
    int j4    = jg * 4;
    int kbase = kk * 32;

    // update-thread mapping (tid < 256)
    int ubi  = tid >> 7;         // 0..1 (valid when tid<256)
    int uhid = tid & 127;
    const float* Gu = g_Gpre + (size_t)(b0 + ubi) * Tt * G4 + uhid;

    const float* wp_s = ws + kbase * G4 + j4;        // smem path (kk<3)
    const float* wp_g = g_whhT + kbase * G4 + j4;    // global path (kk==3)
    const float* h0p  = hs + kbase;
    const float* h1p  = hs + Hh + kbase;

    for (int t = 0; t < Tt; t++) {
        // --- prefetch gate preactivations (consumed after the sync) ---
        float pi = 0.f, pf = 0.f, pgt = 0.f, po = 0.f;
        if (tid < 256) {
            const float* gp = Gu + (size_t)t * G4;
            pi  = __ldg(gp);
            pf  = __ldg(gp + Hh);
            pgt = __ldg(gp + 2 * Hh);
            po  = __ldg(gp + 3 * Hh);
        }

        // --- split-K matvec: 4 gates x 2 batches per thread ---
        float4 a0 = make_float4(0.f, 0.f, 0.f, 0.f);
        float4 a1 = make_float4(0.f, 0.f, 0.f, 0.f);
        if (kk < 3) {
#pragma unroll
            for (int k = 0; k < 32; k += 4) {
                float4 h0 = *(const float4*)(h0p + k);
                float4 h1 = *(const float4*)(h1p + k);
                float4 w0 = *(const float4*)(wp_s + (k + 0) * G4);
                float4 w1 = *(const float4*)(wp_s + (k + 1) * G4);
                float4 w2 = *(const float4*)(wp_s + (k + 2) * G4);
                float4 w3 = *(const float4*)(wp_s + (k + 3) * G4);
                fma4(a0, w0, h0.x); fma4(a1, w0, h1.x);
                fma4(a0, w1, h0.y); fma4(a1, w1, h1.y);
                fma4(a0, w2, h0.z); fma4(a1, w2, h1.z);
                fma4(a0, w3, h0.w); fma4(a1, w3, h1.w);
            }
        } else {
#pragma unroll
            for (int k = 0; k < 32; k += 4) {
                float4 h0 = *(const float4*)(h0p + k);
                float4 h1 = *(const float4*)(h1p + k);
                float4 w0 = __ldg((const float4*)(wp_g + (k + 0) * G4));
                float4 w1 = __ldg((const float4*)(wp_g + (k + 1) * G4));
                float4 w2 = __ldg((const float4*)(wp_g + (k + 2) * G4));
                float4 w3 = __ldg((const float4*)(wp_g + (k + 3) * G4));
                fma4(a0, w0, h0.x); fma4(a1, w0, h1.x);
                fma4(a0, w1, h0.y); fma4(a1, w1, h1.y);
                fma4(a0, w2, h0.z); fma4(a1, w2, h1.z);
                fma4(a0, w3, h0.w); fma4(a1, w3, h1.w);
            }
        }
        *(float4*)(pg + (kk * 2 + 0) * G4 + j4) = a0;
        *(float4*)(pg + (kk * 2 + 1) * G4 + j4) = a1;
        __syncthreads();

        // --- reduce partials + LSTM cell update (256 threads) ---
        if (tid < 256) {
            float gi = pi, gf = pf, gg = pgt, go = po;
#pragma unroll
            for (int q = 0; q < 4; q++) {
                const float* pr = pg + (q * 2 + ubi) * G4 + uhid;
                gi += pr[0];
                gf += pr[Hh];
                gg += pr[2 * Hh];
                go += pr[3 * Hh];
            }
            float cn = sigm(gf) * cs[ubi * Hh + uhid] + sigm(gi) * tanhf(gg);
            float hn = sigm(go) * tanhf(cn);
            cs[ubi * Hh + uhid] = cn;
            hs[ubi * Hh + uhid] = hn;
            Xe[((size_t)(b0 + ubi) * Tt + t) * Hh + uhid] = hn;
        }
        __syncthreads();
    }
}

// ---------------------------------------------------------------------------
extern "C" void kernel_launch(void* const* d_in, const int* in_sizes, int n_in,
                              void* d_out, int out_size) {
    const float* X      = (const float*)d_in[0];
    const float* attn_w = (const float*)d_in[1];
    // d_in[2] = attn_b: dead (softmax shift-invariance), as are attn_w[0:2H]
    const float* w_ih   = (const float*)d_in[3];
    const float* w_hh   = (const float*)d_in[4];
    const float* b_ih   = (const float*)d_in[5];
    const float* b_hh   = (const float*)d_in[6];

    float* out = (float*)d_out;
    float* Xt  = out;                                  // (B,T,N)
    float* Xe  = out + (size_t)Bsz * Tt * Nn;          // (B,T,H)

    const int recur_smem =
        (KC * G4 + 4 * 2 * G4 + 2 * Hh + 2 * Hh) * (int)sizeof(float);  // ~215 KB
    cudaFuncSetAttribute(k_recur, cudaFuncAttributeMaxDynamicSharedMemorySize,
                         recur_smem);

    k_transpose_whh<<<(Hh * G4 + 255) / 256, 256>>>(w_hh);
    k_alpha<<<Bsz, 512>>>(X, attn_w, Xt);
    k_gemm<<<dim3(4, Bsz * Tt / 128), 256>>>(Xt, w_ih, b_ih, b_hh);
    k_recur<<<Bsz / 2, 512, recur_smem>>>(Xe);
}

// round 13
// speedup vs baseline: 2.4073x; 1.6502x over previous
#include <cuda_runtime.h>
#include <cuda_bf16.h>
#include <math.h>
#include <stdint.h>

#define Bsz 256
#define Tt  128
#define Nn  512
#define Hh  128
#define G4  512   // 4*H
#define KC  96    // w_hhT rows resident in recurrence smem

// Device scratch (no runtime alloc)
__device__ float g_Gpre[(size_t)Bsz * Tt * G4];          // 64 MB gate preacts
__device__ float g_whhT[Hh * G4];
__device__ __nv_bfloat16 g_Ahi[(size_t)Bsz * Tt * Nn];   // 32 MB
__device__ __nv_bfloat16 g_Alo[(size_t)Bsz * Tt * Nn];   // 32 MB
__device__ __nv_bfloat16 g_Whi[G4 * Nn];
__device__ __nv_bfloat16 g_Wlo[G4 * Nn];

// ======================= PTX helpers (generic-target only) ==================
__device__ __forceinline__ uint32_t smem_u32(const void* p) {
    uint32_t a;
    asm("{ .reg .u64 t; cvta.to.shared.u64 t, %1; cvt.u32.u64 %0, t; }"
        : "=r"(a) : "l"(p));
    return a;
}
__device__ __forceinline__ void cpa16(uint32_t dst, const void* src) {
    asm volatile("cp.async.cg.shared.global [%0], [%1], 16;"
                 :: "r"(dst), "l"(src) : "memory");
}
__device__ __forceinline__ void cpa_commit() {
    asm volatile("cp.async.commit_group;" ::: "memory");
}
__device__ __forceinline__ void cpa_wait0() {
    asm volatile("cp.async.wait_group 0;" ::: "memory");
}
__device__ __forceinline__ void ldsm4(uint32_t* r, uint32_t a) {
    asm volatile("ldmatrix.sync.aligned.m8n8.x4.shared.b16 {%0,%1,%2,%3}, [%4];"
                 : "=r"(r[0]), "=r"(r[1]), "=r"(r[2]), "=r"(r[3]) : "r"(a));
}
__device__ __forceinline__ void mma16816(float* d, const uint32_t* a,
                                         const uint32_t* b) {
    asm volatile("mma.sync.aligned.m16n8k16.row.col.f32.bf16.bf16.f32 "
        "{%0,%1,%2,%3}, {%4,%5,%6,%7}, {%8,%9}, {%0,%1,%2,%3};"
        : "+f"(d[0]), "+f"(d[1]), "+f"(d[2]), "+f"(d[3])
        : "r"(a[0]), "r"(a[1]), "r"(a[2]), "r"(a[3]), "r"(b[0]), "r"(b[1]));
}
// Swizzled smem address: tile rows of 64B (4 x 16B granules), g = r*4 + c,
// sw(g) = g ^ ((g>>2)&7)  -- bijective, conflict-free for ldmatrix phases.
__device__ __forceinline__ uint32_t sw_addr(uint32_t base, int r, int c) {
    uint32_t g = (uint32_t)(r * 4 + c);
    return base + ((g ^ ((g >> 2) & 7)) << 4);
}

// ---------------------------------------------------------------------------
// w_hh (4H, H) -> w_hhT (H, 4H)
// ---------------------------------------------------------------------------
__global__ void k_transpose_whh(const float* __restrict__ whh) {
    int idx = blockIdx.x * blockDim.x + threadIdx.x;
    if (idx < Hh * G4) {
        int k = idx >> 9;
        int j = idx & 511;
        g_whhT[idx] = whh[j * Hh + k];
    }
}

// ---------------------------------------------------------------------------
// w_ih -> hi/lo bf16 split
// ---------------------------------------------------------------------------
__global__ void k_convert_w(const float* __restrict__ wih) {
    int idx = blockIdx.x * blockDim.x + threadIdx.x;
    if (idx < G4 * Nn) {
        float v = wih[idx];
        __nv_bfloat16 hi = __float2bfloat16(v);
        g_Whi[idx] = hi;
        g_Wlo[idx] = __float2bfloat16(v - __bfloat162float(hi));
    }
}

// ---------------------------------------------------------------------------
// alpha = softmax_n(sum_t X*w_x); Xt = alpha .* X (time-invariant alpha).
// Also emits the hi/lo bf16 split of Xt for the tensor-core GEMM.
// ---------------------------------------------------------------------------
__global__ __launch_bounds__(512) void k_alpha(const float* __restrict__ X,
                                               const float* __restrict__ attn_w,
                                               float* __restrict__ Xt) {
    int b = blockIdx.x;
    int n = threadIdx.x;
    __shared__ float wx[Tt];
    __shared__ float redm[17];
    __shared__ float reds[17];
    if (n < Tt) wx[n] = attn_w[2 * Hh + n];
    __syncthreads();

    const float* Xb = X + (size_t)b * Tt * Nn;
    float acc = 0.f;
#pragma unroll 8
    for (int t = 0; t < Tt; t++)
        acc = fmaf(Xb[t * Nn + n], wx[t], acc);

    float v = acc;
#pragma unroll
    for (int o = 16; o > 0; o >>= 1)
        v = fmaxf(v, __shfl_xor_sync(0xffffffffu, v, o));
    if ((n & 31) == 0) redm[n >> 5] = v;
    __syncthreads();
    if (n < 32) {
        float m = (n < 16) ? redm[n] : -3.402823466e38f;
#pragma unroll
        for (int o = 16; o > 0; o >>= 1)
            m = fmaxf(m, __shfl_xor_sync(0xffffffffu, m, o));
        if (n == 0) redm[16] = m;
    }
    __syncthreads();
    float mx = redm[16];

    float e = __expf(acc - mx);
    v = e;
#pragma unroll
    for (int o = 16; o > 0; o >>= 1)
        v += __shfl_xor_sync(0xffffffffu, v, o);
    if ((n & 31) == 0) reds[n >> 5] = v;
    __syncthreads();
    if (n < 32) {
        float s = (n < 16) ? reds[n] : 0.f;
#pragma unroll
        for (int o = 16; o > 0; o >>= 1)
            s += __shfl_xor_sync(0xffffffffu, s, o);
        if (n == 0) reds[16] = s;
    }
    __syncthreads();
    float alpha = e / reds[16];

    float* Ot = Xt + (size_t)b * Tt * Nn;
    __nv_bfloat16* Ah = g_Ahi + (size_t)b * Tt * Nn;
    __nv_bfloat16* Al = g_Alo + (size_t)b * Tt * Nn;
#pragma unroll 4
    for (int t = 0; t < Tt; t++) {
        float xv = alpha * Xb[t * Nn + n];
        Ot[t * Nn + n] = xv;
        __nv_bfloat16 hi = __float2bfloat16(xv);
        Ah[t * Nn + n] = hi;
        Al[t * Nn + n] = __float2bfloat16(xv - __bfloat162float(hi));
    }
}

// ---------------------------------------------------------------------------
// bf16x3 warp-MMA GEMM (mma.sync m16n8k16, generic PTX — no tcgen05):
//   Gpre[m,j] = sum_k Xt[m,k]*w_ih[j,k] + bias[j]
//   D = Ahi*Bhi^T + Ahi*Blo^T + Alo*Bhi^T   (fp32 register accumulate)
// CTA tile 128x128, K-chunks of 32 double-buffered via cp.async.
// 8 warps, warp tile 64x32 (warp_m = wid&1, warp_n = wid>>2..): 4x4 frags.
// Grid (4 n-tiles inner, 256 m-tiles) so co-resident CTAs reuse A via L2.
// ---------------------------------------------------------------------------
#define CHUNK_BYTES 32768        // 4 tiles x 8 KB (Ahi, Alo, Bhi, Blo)
#define GT_SMEM (2 * CHUNK_BYTES)

__device__ __forceinline__ void stage_chunk(uint32_t bbase, int kc, int tid,
                                            const __nv_bfloat16* PAh,
                                            const __nv_bfloat16* PAl,
                                            const __nv_bfloat16* PBh,
                                            const __nv_bfloat16* PBl) {
    const __nv_bfloat16* P[4] = { PAh, PAl, PBh, PBl };
#pragma unroll
    for (int t = 0; t < 4; t++) {
        uint32_t toff = bbase + t * 8192;
#pragma unroll
        for (int q = 0; q < 2; q++) {
            uint32_t G = (uint32_t)tid + q * 256;   // granule 0..511
            uint32_t r = G >> 2, c = G & 3;
            uint32_t swg = G ^ ((G >> 2) & 7);
            cpa16(toff + (swg << 4), P[t] + (size_t)r * 512 + kc * 32 + c * 8);
        }
    }
}

__global__ __launch_bounds__(256) void k_gemm_mma(const float* __restrict__ bih,
                                                  const float* __restrict__ bhh) {
    extern __shared__ char smp[];
    uint32_t sb = smem_u32(smp);
    int tid  = threadIdx.x;
    int lane = tid & 31;
    int wid  = tid >> 5;
    int bn   = blockIdx.x;   // 0..3
    int bm   = blockIdx.y;   // 0..255
    int m0w  = (wid & 1) * 64;
    int n0w  = (wid >> 1) * 32;

    const __nv_bfloat16* PAh = g_Ahi + (size_t)bm * 128 * 512;
    const __nv_bfloat16* PAl = g_Alo + (size_t)bm * 128 * 512;
    const __nv_bfloat16* PBh = g_Whi + (size_t)bn * 128 * 512;
    const __nv_bfloat16* PBl = g_Wlo + (size_t)bn * 128 * 512;

    float d[4][4][4];
#pragma unroll
    for (int i = 0; i < 4; i++)
#pragma unroll
        for (int j = 0; j < 4; j++)
#pragma unroll
            for (int q = 0; q < 4; q++) d[i][j][q] = 0.f;

    stage_chunk(sb, 0, tid, PAh, PAl, PBh, PBl);
    cpa_commit();

    int buf = 0;
    for (int kc = 0; kc < 16; kc++) {
        cpa_wait0();
        __syncthreads();
        if (kc + 1 < 16) {
            stage_chunk(sb + (buf ^ 1) * CHUNK_BYTES, kc + 1, tid,
                        PAh, PAl, PBh, PBl);
            cpa_commit();
        }
        uint32_t Ah = sb + buf * CHUNK_BYTES;
        uint32_t Al = Ah + 8192;
        uint32_t Bh = Ah + 16384;
        uint32_t Bl = Ah + 24576;

#pragma unroll
        for (int s = 0; s < 2; s++) {        // two K=16 steps per chunk
            uint32_t bh[4][2], bl[4][2];
#pragma unroll
            for (int jp = 0; jp < 2; jp++) { // each x4 covers 2 n-frags
                uint32_t tmp[4];
                int rowb = n0w + jp * 16 + (lane & 7) + ((lane >> 4) << 3);
                int cb   = s * 2 + ((lane >> 3) & 1);
                ldsm4(tmp, sw_addr(Bh, rowb, cb));
                bh[jp * 2][0] = tmp[0]; bh[jp * 2][1] = tmp[1];
                bh[jp * 2 + 1][0] = tmp[2]; bh[jp * 2 + 1][1] = tmp[3];
                ldsm4(tmp, sw_addr(Bl, rowb, cb));
                bl[jp * 2][0] = tmp[0]; bl[jp * 2][1] = tmp[1];
                bl[jp * 2 + 1][0] = tmp[2]; bl[jp * 2 + 1][1] = tmp[3];
            }
#pragma unroll
            for (int i = 0; i < 4; i++) {
                uint32_t ah[4], al[4];
                int rowa = m0w + i * 16 + (lane & 15);
                int ca   = s * 2 + (lane >> 4);
                ldsm4(ah, sw_addr(Ah, rowa, ca));
                ldsm4(al, sw_addr(Al, rowa, ca));
#pragma unroll
                for (int j = 0; j < 4; j++) {
                    mma16816(d[i][j], ah, bh[j]);
                    mma16816(d[i][j], ah, bl[j]);
                    mma16816(d[i][j], al, bh[j]);
                }
            }
        }
        buf ^= 1;
    }

    // Epilogue: bias add + fp32 store.
    // Frag (i,j): d0,d1 -> row l>>2, cols (l&3)*2 + {0,1}; d2,d3 -> row+8.
#pragma unroll
    for (int j = 0; j < 4; j++) {
        int col = bn * 128 + n0w + j * 8 + (lane & 3) * 2;
        float b0 = bih[col] + bhh[col];
        float b1 = bih[col + 1] + bhh[col + 1];
#pragma unroll
        for (int i = 0; i < 4; i++) {
            int row = bm * 128 + m0w + i * 16 + (lane >> 2);
            float2 v0 = make_float2(d[i][j][0] + b0, d[i][j][1] + b1);
            float2 v1 = make_float2(d[i][j][2] + b0, d[i][j][3] + b1);
            *(float2*)(g_Gpre + (size_t)row * 512 + col) = v0;
            *(float2*)(g_Gpre + (size_t)(row + 8) * 512 + col) = v1;
        }
    }
}

// ---------------------------------------------------------------------------
// LSTM recurrence (R10's validated split-K design, unchanged).
// ---------------------------------------------------------------------------
__device__ __forceinline__ float sigm(float x) { return 1.f / (1.f + __expf(-x)); }

__device__ __forceinline__ void fma4(float4& acc, const float4& wv, float hv) {
    acc.x = fmaf(wv.x, hv, acc.x);
    acc.y = fmaf(wv.y, hv, acc.y);
    acc.z = fmaf(wv.z, hv, acc.z);
    acc.w = fmaf(wv.w, hv, acc.w);
}

__global__ __launch_bounds__(512) void k_recur(float* __restrict__ Xe) {
    extern __shared__ float sm[];
    float* ws = sm;                     // [KC][512]
    float* pg = ws + KC * G4;           // [4][2][512] partials
    float* hs = pg + 4 * 2 * G4;        // [2][128]
    float* cs = hs + 2 * Hh;            // [2][128]

    int tid = threadIdx.x;
    int b0  = blockIdx.x * 2;

    for (int i = tid; i < KC * G4 / 4; i += 512)
        ((float4*)ws)[i] = ((const float4*)g_whhT)[i];
    if (tid < 2 * Hh) { hs[tid] = 0.f; cs[tid] = 0.f; }
    __syncthreads();

    int kk    = tid >> 7;
    int jg    = tid & 127;
    int j4    = jg * 4;
    int kbase = kk * 32;

    int ubi  = tid >> 7;
    int uhid = tid & 127;
    const float* Gu = g_Gpre + (size_t)(b0 + ubi) * Tt * G4 + uhid;

    const float* wp_s = ws + kbase * G4 + j4;
    const float* wp_g = g_whhT + kbase * G4 + j4;
    const float* h0p  = hs + kbase;
    const float* h1p  = hs + Hh + kbase;

    for (int t = 0; t < Tt; t++) {
        float pi = 0.f, pf = 0.f, pgt = 0.f, po = 0.f;
        if (tid < 256) {
            const float* gp = Gu + (size_t)t * G4;
            pi  = __ldg(gp);
            pf  = __ldg(gp + Hh);
            pgt = __ldg(gp + 2 * Hh);
            po  = __ldg(gp + 3 * Hh);
        }

        float4 a0 = make_float4(0.f, 0.f, 0.f, 0.f);
        float4 a1 = make_float4(0.f, 0.f, 0.f, 0.f);
        if (kk < 3) {
#pragma unroll
            for (int k = 0; k < 32; k += 4) {
                float4 h0 = *(const float4*)(h0p + k);
                float4 h1 = *(const float4*)(h1p + k);
                float4 w0 = *(const float4*)(wp_s + (k + 0) * G4);
                float4 w1 = *(const float4*)(wp_s + (k + 1) * G4);
                float4 w2 = *(const float4*)(wp_s + (k + 2) * G4);
                float4 w3 = *(const float4*)(wp_s + (k + 3) * G4);
                fma4(a0, w0, h0.x); fma4(a1, w0, h1.x);
                fma4(a0, w1, h0.y); fma4(a1, w1, h1.y);
                fma4(a0, w2, h0.z); fma4(a1, w2, h1.z);
                fma4(a0, w3, h0.w); fma4(a1, w3, h1.w);
            }
        } else {
#pragma unroll
            for (int k = 0; k < 32; k += 4) {
                float4 h0 = *(const float4*)(h0p + k);
                float4 h1 = *(const float4*)(h1p + k);
                float4 w0 = __ldg((const float4*)(wp_g + (k + 0) * G4));
                float4 w1 = __ldg((const float4*)(wp_g + (k + 1) * G4));
                float4 w2 = __ldg((const float4*)(wp_g + (k + 2) * G4));
                float4 w3 = __ldg((const float4*)(wp_g + (k + 3) * G4));
                fma4(a0, w0, h0.x); fma4(a1, w0, h1.x);
                fma4(a0, w1, h0.y); fma4(a1, w1, h1.y);
                fma4(a0, w2, h0.z); fma4(a1, w2, h1.z);
                fma4(a0, w3, h0.w); fma4(a1, w3, h1.w);
            }
        }
        *(float4*)(pg + (kk * 2 + 0) * G4 + j4) = a0;
        *(float4*)(pg + (kk * 2 + 1) * G4 + j4) = a1;
        __syncthreads();

        if (tid < 256) {
            float gi = pi, gf = pf, gg = pgt, go = po;
#pragma unroll
            for (int q = 0; q < 4; q++) {
                const float* pr = pg + (q * 2 + ubi) * G4 + uhid;
                gi += pr[0];
                gf += pr[Hh];
                gg += pr[2 * Hh];
                go += pr[3 * Hh];
            }
            float cn = sigm(gf) * cs[ubi * Hh + uhid] + sigm(gi) * tanhf(gg);
            float hn = sigm(go) * tanhf(cn);
            cs[ubi * Hh + uhid] = cn;
            hs[ubi * Hh + uhid] = hn;
            Xe[((size_t)(b0 + ubi) * Tt + t) * Hh + uhid] = hn;
        }
        __syncthreads();
    }
}

// ---------------------------------------------------------------------------
extern "C" void kernel_launch(void* const* d_in, const int* in_sizes, int n_in,
                              void* d_out, int out_size) {
    const float* X      = (const float*)d_in[0];
    const float* attn_w = (const float*)d_in[1];
    // d_in[2] = attn_b: dead (softmax shift-invariance), as are attn_w[0:2H]
    const float* w_ih   = (const float*)d_in[3];
    const float* w_hh   = (const float*)d_in[4];
    const float* b_ih   = (const float*)d_in[5];
    const float* b_hh   = (const float*)d_in[6];

    float* out = (float*)d_out;
    float* Xt  = out;                                  // (B,T,N)
    float* Xe  = out + (size_t)Bsz * Tt * Nn;          // (B,T,H)

    const int recur_smem =
        (KC * G4 + 4 * 2 * G4 + 2 * Hh + 2 * Hh) * (int)sizeof(float);
    cudaFuncSetAttribute(k_recur, cudaFuncAttributeMaxDynamicSharedMemorySize,
                         recur_smem);
    cudaFuncSetAttribute(k_gemm_mma, cudaFuncAttributeMaxDynamicSharedMemorySize,
                         GT_SMEM);

    k_transpose_whh<<<(Hh * G4 + 255) / 256, 256>>>(w_hh);
    k_convert_w<<<(G4 * Nn + 255) / 256, 256>>>(w_ih);
    k_alpha<<<Bsz, 512>>>(X, attn_w, Xt);
    k_gemm_mma<<<dim3(4, Bsz * Tt / 128), 256, GT_SMEM>>>(b_ih, b_hh);
    k_recur<<<Bsz / 2, 512, recur_smem>>>(Xe);
}

// round 14
// speedup vs baseline: 2.7936x; 1.1605x over previous
#include <cuda_runtime.h>
#include <cuda_bf16.h>
#include <math.h>
#include <stdint.h>

#define Bsz 256
#define Tt  128
#define Nn  512
#define Hh  128
#define G4  512   // 4*H

// Device scratch (no runtime alloc)
__device__ float g_Gpre[(size_t)Bsz * Tt * G4];          // 64 MB gate preacts
__device__ float g_whhT[Hh * G4];
__device__ __nv_bfloat16 g_Ahi[(size_t)Bsz * Tt * Nn];   // 32 MB
__device__ __nv_bfloat16 g_Alo[(size_t)Bsz * Tt * Nn];   // 32 MB
__device__ __nv_bfloat16 g_Whi[G4 * Nn];
__device__ __nv_bfloat16 g_Wlo[G4 * Nn];

// ======================= PTX helpers (generic-target only) ==================
__device__ __forceinline__ uint32_t smem_u32(const void* p) {
    uint32_t a;
    asm("{ .reg .u64 t; cvta.to.shared.u64 t, %1; cvt.u32.u64 %0, t; }"
        : "=r"(a) : "l"(p));
    return a;
}
__device__ __forceinline__ void cpa16(uint32_t dst, const void* src) {
    asm volatile("cp.async.cg.shared.global [%0], [%1], 16;"
                 :: "r"(dst), "l"(src) : "memory");
}
__device__ __forceinline__ void cpa_commit() {
    asm volatile("cp.async.commit_group;" ::: "memory");
}
__device__ __forceinline__ void cpa_wait0() {
    asm volatile("cp.async.wait_group 0;" ::: "memory");
}
__device__ __forceinline__ void ldsm4(uint32_t* r, uint32_t a) {
    asm volatile("ldmatrix.sync.aligned.m8n8.x4.shared.b16 {%0,%1,%2,%3}, [%4];"
                 : "=r"(r[0]), "=r"(r[1]), "=r"(r[2]), "=r"(r[3]) : "r"(a));
}
__device__ __forceinline__ void mma16816(float* d, const uint32_t* a,
                                         const uint32_t* b) {
    asm volatile("mma.sync.aligned.m16n8k16.row.col.f32.bf16.bf16.f32 "
        "{%0,%1,%2,%3}, {%4,%5,%6,%7}, {%8,%9}, {%0,%1,%2,%3};"
        : "+f"(d[0]), "+f"(d[1]), "+f"(d[2]), "+f"(d[3])
        : "r"(a[0]), "r"(a[1]), "r"(a[2]), "r"(a[3]), "r"(b[0]), "r"(b[1]));
}
// Packed fp32x2 FMA (B300 2x fp32 path; PTX >= 8.6, sm_100+, non-suffixed ISA)
__device__ __forceinline__ void fma2(unsigned long long& d,
                                     unsigned long long a, unsigned long long b) {
    asm("fma.rn.f32x2 %0, %1, %2, %0;" : "+l"(d) : "l"(a), "l"(b));
}
__device__ __forceinline__ unsigned long long dup2(float v) {
    unsigned long long r;
    asm("mov.b64 %0, {%1, %1};" : "=l"(r) : "f"(v));
    return r;
}
// Swizzled smem address: tile rows of 64B (4 x 16B granules), g = r*4 + c,
// sw(g) = g ^ ((g>>2)&7)  -- bijective, conflict-free for ldmatrix phases.
__device__ __forceinline__ uint32_t sw_addr(uint32_t base, int r, int c) {
    uint32_t g = (uint32_t)(r * 4 + c);
    return base + ((g ^ ((g >> 2) & 7)) << 4);
}

// ---------------------------------------------------------------------------
// w_hh (4H, H) -> w_hhT (H, 4H)
// ---------------------------------------------------------------------------
__global__ void k_transpose_whh(const float* __restrict__ whh) {
    int idx = blockIdx.x * blockDim.x + threadIdx.x;
    if (idx < Hh * G4) {
        int k = idx >> 9;
        int j = idx & 511;
        g_whhT[idx] = whh[j * Hh + k];
    }
}

// ---------------------------------------------------------------------------
// w_ih -> hi/lo bf16 split
// ---------------------------------------------------------------------------
__global__ void k_convert_w(const float* __restrict__ wih) {
    int idx = blockIdx.x * blockDim.x + threadIdx.x;
    if (idx < G4 * Nn) {
        float v = wih[idx];
        __nv_bfloat16 hi = __float2bfloat16(v);
        g_Whi[idx] = hi;
        g_Wlo[idx] = __float2bfloat16(v - __bfloat162float(hi));
    }
}

// ---------------------------------------------------------------------------
// alpha = softmax_n(sum_t X*w_x); Xt = alpha .* X (time-invariant alpha).
// Also emits the hi/lo bf16 split of Xt for the tensor-core GEMM.
// ---------------------------------------------------------------------------
__global__ __launch_bounds__(512) void k_alpha(const float* __restrict__ X,
                                               const float* __restrict__ attn_w,
                                               float* __restrict__ Xt) {
    int b = blockIdx.x;
    int n = threadIdx.x;
    __shared__ float wx[Tt];
    __shared__ float redm[17];
    __shared__ float reds[17];
    if (n < Tt) wx[n] = attn_w[2 * Hh + n];
    __syncthreads();

    const float* Xb = X + (size_t)b * Tt * Nn;
    float acc = 0.f;
#pragma unroll 8
    for (int t = 0; t < Tt; t++)
        acc = fmaf(Xb[t * Nn + n], wx[t], acc);

    float v = acc;
#pragma unroll
    for (int o = 16; o > 0; o >>= 1)
        v = fmaxf(v, __shfl_xor_sync(0xffffffffu, v, o));
    if ((n & 31) == 0) redm[n >> 5] = v;
    __syncthreads();
    if (n < 32) {
        float m = (n < 16) ? redm[n] : -3.402823466e38f;
#pragma unroll
        for (int o = 16; o > 0; o >>= 1)
            m = fmaxf(m, __shfl_xor_sync(0xffffffffu, m, o));
        if (n == 0) redm[16] = m;
    }
    __syncthreads();
    float mx = redm[16];

    float e = __expf(acc - mx);
    v = e;
#pragma unroll
    for (int o = 16; o > 0; o >>= 1)
        v += __shfl_xor_sync(0xffffffffu, v, o);
    if ((n & 31) == 0) reds[n >> 5] = v;
    __syncthreads();
    if (n < 32) {
        float s = (n < 16) ? reds[n] : 0.f;
#pragma unroll
        for (int o = 16; o > 0; o >>= 1)
            s += __shfl_xor_sync(0xffffffffu, s, o);
        if (n == 0) reds[16] = s;
    }
    __syncthreads();
    float alpha = e / reds[16];

    float* Ot = Xt + (size_t)b * Tt * Nn;
    __nv_bfloat16* Ah = g_Ahi + (size_t)b * Tt * Nn;
    __nv_bfloat16* Al = g_Alo + (size_t)b * Tt * Nn;
#pragma unroll 4
    for (int t = 0; t < Tt; t++) {
        float xv = alpha * Xb[t * Nn + n];
        Ot[t * Nn + n] = xv;
        __nv_bfloat16 hi = __float2bfloat16(xv);
        Ah[t * Nn + n] = hi;
        Al[t * Nn + n] = __float2bfloat16(xv - __bfloat162float(hi));
    }
}

// ---------------------------------------------------------------------------
// bf16x3 warp-MMA GEMM (unchanged from R13 — validated, tensor=67.5%).
// ---------------------------------------------------------------------------
#define CHUNK_BYTES 32768        // 4 tiles x 8 KB (Ahi, Alo, Bhi, Blo)
#define GT_SMEM (2 * CHUNK_BYTES)

__device__ __forceinline__ void stage_chunk(uint32_t bbase, int kc, int tid,
                                            const __nv_bfloat16* PAh,
                                            const __nv_bfloat16* PAl,
                                            const __nv_bfloat16* PBh,
                                            const __nv_bfloat16* PBl) {
    const __nv_bfloat16* P[4] = { PAh, PAl, PBh, PBl };
#pragma unroll
    for (int t = 0; t < 4; t++) {
        uint32_t toff = bbase + t * 8192;
#pragma unroll
        for (int q = 0; q < 2; q++) {
            uint32_t G = (uint32_t)tid + q * 256;   // granule 0..511
            uint32_t r = G >> 2, c = G & 3;
            uint32_t swg = G ^ ((G >> 2) & 7);
            cpa16(toff + (swg << 4), P[t] + (size_t)r * 512 + kc * 32 + c * 8);
        }
    }
}

__global__ __launch_bounds__(256) void k_gemm_mma(const float* __restrict__ bih,
                                                  const float* __restrict__ bhh) {
    extern __shared__ char smp[];
    uint32_t sb = smem_u32(smp);
    int tid  = threadIdx.x;
    int lane = tid & 31;
    int wid  = tid >> 5;
    int bn   = blockIdx.x;   // 0..3
    int bm   = blockIdx.y;   // 0..255
    int m0w  = (wid & 1) * 64;
    int n0w  = (wid >> 1) * 32;

    const __nv_bfloat16* PAh = g_Ahi + (size_t)bm * 128 * 512;
    const __nv_bfloat16* PAl = g_Alo + (size_t)bm * 128 * 512;
    const __nv_bfloat16* PBh = g_Whi + (size_t)bn * 128 * 512;
    const __nv_bfloat16* PBl = g_Wlo + (size_t)bn * 128 * 512;

    float d[4][4][4];
#pragma unroll
    for (int i = 0; i < 4; i++)
#pragma unroll
        for (int j = 0; j < 4; j++)
#pragma unroll
            for (int q = 0; q < 4; q++) d[i][j][q] = 0.f;

    stage_chunk(sb, 0, tid, PAh, PAl, PBh, PBl);
    cpa_commit();

    int buf = 0;
    for (int kc = 0; kc < 16; kc++) {
        cpa_wait0();
        __syncthreads();
        if (kc + 1 < 16) {
            stage_chunk(sb + (buf ^ 1) * CHUNK_BYTES, kc + 1, tid,
                        PAh, PAl, PBh, PBl);
            cpa_commit();
        }
        uint32_t Ah = sb + buf * CHUNK_BYTES;
        uint32_t Al = Ah + 8192;
        uint32_t Bh = Ah + 16384;
        uint32_t Bl = Ah + 24576;

#pragma unroll
        for (int s = 0; s < 2; s++) {        // two K=16 steps per chunk
            uint32_t bh[4][2], bl[4][2];
#pragma unroll
            for (int jp = 0; jp < 2; jp++) { // each x4 covers 2 n-frags
                uint32_t tmp[4];
                int rowb = n0w + jp * 16 + (lane & 7) + ((lane >> 4) << 3);
                int cb   = s * 2 + ((lane >> 3) & 1);
                ldsm4(tmp, sw_addr(Bh, rowb, cb));
                bh[jp * 2][0] = tmp[0]; bh[jp * 2][1] = tmp[1];
                bh[jp * 2 + 1][0] = tmp[2]; bh[jp * 2 + 1][1] = tmp[3];
                ldsm4(tmp, sw_addr(Bl, rowb, cb));
                bl[jp * 2][0] = tmp[0]; bl[jp * 2][1] = tmp[1];
                bl[jp * 2 + 1][0] = tmp[2]; bl[jp * 2 + 1][1] = tmp[3];
            }
#pragma unroll
            for (int i = 0; i < 4; i++) {
                uint32_t ah[4], al[4];
                int rowa = m0w + i * 16 + (lane & 15);
                int ca   = s * 2 + (lane >> 4);
                ldsm4(ah, sw_addr(Ah, rowa, ca));
                ldsm4(al, sw_addr(Al, rowa, ca));
#pragma unroll
                for (int j = 0; j < 4; j++) {
                    mma16816(d[i][j], ah, bh[j]);
                    mma16816(d[i][j], ah, bl[j]);
                    mma16816(d[i][j], al, bh[j]);
                }
            }
        }
        buf ^= 1;
    }

    // Epilogue: bias add + fp32 store.
#pragma unroll
    for (int j = 0; j < 4; j++) {
        int col = bn * 128 + n0w + j * 8 + (lane & 3) * 2;
        float b0 = bih[col] + bhh[col];
        float b1 = bih[col + 1] + bhh[col + 1];
#pragma unroll
        for (int i = 0; i < 4; i++) {
            int row = bm * 128 + m0w + i * 16 + (lane >> 2);
            float2 v0 = make_float2(d[i][j][0] + b0, d[i][j][1] + b1);
            float2 v1 = make_float2(d[i][j][2] + b0, d[i][j][3] + b1);
            *(float2*)(g_Gpre + (size_t)row * 512 + col) = v0;
            *(float2*)(g_Gpre + (size_t)(row + 8) * 512 + col) = v1;
        }
    }
}

// ---------------------------------------------------------------------------
// LSTM recurrence v3: split-K + packed f32x2 FMA + register-resident weights.
// 128 blocks x 2 batches, 512 threads, 128 regs (launch_bounds(512,1)).
//   thread (kk = tid>>7, jg = tid&127): gate quad j4 = jg*4 (2 f32x2 pairs),
//   both batches, k-slice [kk*32, kk*32+32).
//   k in [kbase, kbase+16): weights in REGISTERS (64 regs, loaded once).
//   k in [kbase+16, kbase+32): weights from smem (128 KB total -> 1024-cyc
//   crossbar/step).  h duplicated {h,h} in hs2 by the update threads so the
//   weight pairs (contiguous in w_hhT) multiply with zero pack instructions.
//   FFMA2 floor: 128 packed-FMA/thread -> ~1024 cyc/step/SMSP.
// ---------------------------------------------------------------------------
#define RSM_W (4 * 16 * G4)   // 32768 floats of smem weights (128 KB)

__device__ __forceinline__ float sigm(float x) { return 1.f / (1.f + __expf(-x)); }

__global__ __launch_bounds__(512, 1) void k_recur(float* __restrict__ Xe) {
    extern __shared__ float sm[];
    float* ws = sm;                                   // [4][16][512]
    float* pg = ws + RSM_W;                           // [8][512] partials
    float* cs = pg + 8 * G4;                          // [2][128]
    unsigned long long* hs2 =
        (unsigned long long*)(cs + 2 * Hh);           // [2][128] {h,h} packed

    int tid = threadIdx.x;
    int b0  = blockIdx.x * 2;
    int kk    = tid >> 7;
    int jg    = tid & 127;
    int j4    = jg * 4;
    int kbase = kk * 32;

    // stage smem weight half: ws row r (0..63) <- g_whhT row kk*32+16+(r&15)
    for (int i = tid; i < RSM_W / 4; i += 512) {
        int r = i >> 7;          // 128 float4 granules per row
        int c = i & 127;
        int grow = (r >> 4) * 32 + 16 + (r & 15);
        ((float4*)ws)[i] = *(const float4*)(g_whhT + (size_t)grow * 512 + c * 4);
    }
    if (tid < 256) {
        cs[tid] = 0.f;
        hs2[tid] = 0ull;
    }

    // register weight half: k in [kbase, kbase+16)
    ulonglong2 wreg[16];
#pragma unroll
    for (int kr = 0; kr < 16; kr++)
        wreg[kr] = *(const ulonglong2*)(g_whhT + (size_t)(kbase + kr) * 512 + j4);
    __syncthreads();

    int ubi  = tid >> 7;          // valid when tid<256
    int uhid = tid & 127;
    const float* Gu = g_Gpre + (size_t)(b0 + ubi) * Tt * G4 + uhid;

    const unsigned long long* h0 = hs2;
    const unsigned long long* h1 = hs2 + Hh;
    const float* wsm_t = ws + (size_t)(kk * 16) * G4 + j4;

    for (int t = 0; t < Tt; t++) {
        // prefetch gate preactivations (resolve under the matvec)
        float pi = 0.f, pf = 0.f, pgt = 0.f, po = 0.f;
        if (tid < 256) {
            const float* gp = Gu + (size_t)t * G4;
            pi  = __ldg(gp);
            pf  = __ldg(gp + Hh);
            pgt = __ldg(gp + 2 * Hh);
            po  = __ldg(gp + 3 * Hh);
        }

        ulonglong2 a0, a1;
        a0.x = 0ull; a0.y = 0ull; a1.x = 0ull; a1.y = 0ull;

        // ---- register-weight half ----
#pragma unroll
        for (int kr = 0; kr < 16; kr += 2) {
            ulonglong2 hh0 = *(const ulonglong2*)(h0 + kbase + kr);
            ulonglong2 hh1 = *(const ulonglong2*)(h1 + kbase + kr);
            fma2(a0.x, wreg[kr].x, hh0.x);     fma2(a0.y, wreg[kr].y, hh0.x);
            fma2(a1.x, wreg[kr].x, hh1.x);     fma2(a1.y, wreg[kr].y, hh1.x);
            fma2(a0.x, wreg[kr + 1].x, hh0.y); fma2(a0.y, wreg[kr + 1].y, hh0.y);
            fma2(a1.x, wreg[kr + 1].x, hh1.y); fma2(a1.y, wreg[kr + 1].y, hh1.y);
        }
        // ---- smem-weight half ----
#pragma unroll
        for (int kr = 0; kr < 16; kr += 2) {
            ulonglong2 hh0 = *(const ulonglong2*)(h0 + kbase + 16 + kr);
            ulonglong2 hh1 = *(const ulonglong2*)(h1 + kbase + 16 + kr);
            ulonglong2 w0 = *(const ulonglong2*)(wsm_t + (size_t)(kr + 0) * G4);
            ulonglong2 w1 = *(const ulonglong2*)(wsm_t + (size_t)(kr + 1) * G4);
            fma2(a0.x, w0.x, hh0.x); fma2(a0.y, w0.y, hh0.x);
            fma2(a1.x, w0.x, hh1.x); fma2(a1.y, w0.y, hh1.x);
            fma2(a0.x, w1.x, hh0.y); fma2(a0.y, w1.y, hh0.y);
            fma2(a1.x, w1.x, hh1.y); fma2(a1.y, w1.y, hh1.y);
        }
        *(ulonglong2*)(pg + (kk * 2 + 0) * G4 + j4) = a0;
        *(ulonglong2*)(pg + (kk * 2 + 1) * G4 + j4) = a1;
        __syncthreads();

        // ---- reduce partials + LSTM cell update (256 threads) ----
        if (tid < 256) {
            float gi = pi, gf = pf, gg = pgt, go = po;
#pragma unroll
            for (int q = 0; q < 4; q++) {
                const float* pr = pg + (q * 2 + ubi) * G4 + uhid;
                gi += pr[0];
                gf += pr[Hh];
                gg += pr[2 * Hh];
                go += pr[3 * Hh];
            }
            float cn = sigm(gf) * cs[ubi * Hh + uhid] + sigm(gi) * tanhf(gg);
            float hn = sigm(go) * tanhf(cn);
            cs[ubi * Hh + uhid] = cn;
            hs2[ubi * Hh + uhid] = dup2(hn);
            Xe[((size_t)(b0 + ubi) * Tt + t) * Hh + uhid] = hn;
        }
        __syncthreads();
    }
}

// ---------------------------------------------------------------------------
extern "C" void kernel_launch(void* const* d_in, const int* in_sizes, int n_in,
                              void* d_out, int out_size) {
    const float* X      = (const float*)d_in[0];
    const float* attn_w = (const float*)d_in[1];
    // d_in[2] = attn_b: dead (softmax shift-invariance), as are attn_w[0:2H]
    const float* w_ih   = (const float*)d_in[3];
    const float* w_hh   = (const float*)d_in[4];
    const float* b_ih   = (const float*)d_in[5];
    const float* b_hh   = (const float*)d_in[6];

    float* out = (float*)d_out;
    float* Xt  = out;                                  // (B,T,N)
    float* Xe  = out + (size_t)Bsz * Tt * Nn;          // (B,T,H)

    const int recur_smem =
        (RSM_W + 8 * G4 + 2 * Hh) * (int)sizeof(float) + 2 * Hh * 8;  // 150528 B
    cudaFuncSetAttribute(k_recur, cudaFuncAttributeMaxDynamicSharedMemorySize,
                         recur_smem);
    cudaFuncSetAttribute(k_gemm_mma, cudaFuncAttributeMaxDynamicSharedMemorySize,
                         GT_SMEM);

    k_transpose_whh<<<(Hh * G4 + 255) / 256, 256>>>(w_hh);
    k_convert_w<<<(G4 * Nn + 255) / 256, 256>>>(w_ih);
    k_alpha<<<Bsz, 512>>>(X, attn_w, Xt);
    k_gemm_mma<<<dim3(4, Bsz * Tt / 128), 256, GT_SMEM>>>(b_ih, b_hh);
    k_recur<<<Bsz / 2, 512, recur_smem>>>(Xe);
}